// round 7
// baseline (speedup 1.0000x reference)
#include <cuda_runtime.h>
#include <math.h>

#define BATCH 16
#define CCH   256
#define HWSZ  16384
#define RED   64
#define MID   32
#define NWIN  4096
#define ATT_SCALE 0.35355339059327373f   // 8^-0.5

typedef unsigned long long u64t;

// Folded weights (prepared by k_prep). Wd arrays are lane-duplicated u64.
__device__ u64t  g_W1d[CCH * RED];    // [c][o] dup'd
__device__ float g_b1[RED];
__device__ u64t  g_W2d[RED * CCH];    // [r][o] dup'd
__device__ float g_b2[CCH];
__device__ u64t  g_Wqkd[MID * 64];    // [k][o] dup'd (o<32 q, o>=32 k)
__device__ float g_bqk[64];

__device__ __forceinline__ u64t pk(float a) {
    u64t r; asm("mov.b64 %0, {%1,%1};" : "=l"(r) : "f"(a)); return r;
}
__device__ __forceinline__ void f2fma(u64t& d, u64t a, u64t b) {
    asm("fma.rn.f32x2 %0, %1, %2, %0;" : "+l"(d) : "l"(a), "l"(b));
}
__device__ __forceinline__ void f2add(u64t& d, u64t a) {
    asm("add.rn.f32x2 %0, %0, %1;" : "+l"(d) : "l"(a));
}
__device__ __forceinline__ float2 up(u64t a) {
    float2 f; asm("mov.b64 {%0, %1}, %2;" : "=f"(f.x), "=f"(f.y) : "l"(a)); return f;
}

// ---------------------------------------------------------------------------
__global__ void k_prep(const float* __restrict__ gin,  const float* __restrict__ bin,
                       const float* __restrict__ min_, const float* __restrict__ vin,
                       const float* __restrict__ w_in, const float* __restrict__ w_out,
                       const float* __restrict__ gout, const float* __restrict__ bout,
                       const float* __restrict__ mout, const float* __restrict__ vout,
                       const float* __restrict__ alpha,
                       const float* __restrict__ qh,   const float* __restrict__ qb,
                       const float* __restrict__ kh,   const float* __restrict__ kb)
{
    int tid = threadIdx.x;
    float s = 1.f / (1.f + expf(-alpha[0]));

    for (int idx = tid; idx < CCH * RED; idx += 256) {
        int c = idx >> 6, o = idx & 63;
        float inv = gin[c] * rsqrtf(vin[c] + 1e-5f);
        g_W1d[idx] = pk(w_in[o * CCH + c] * inv);
    }
    if (tid < RED) {
        float a = 0.f;
        for (int c = 0; c < CCH; c++) {
            float inv = gin[c] * rsqrtf(vin[c] + 1e-5f);
            a += w_in[tid * CCH + c] * (bin[c] - min_[c] * inv);
        }
        g_b1[tid] = a;
    }
    for (int idx = tid; idx < RED * CCH; idx += 256) {
        int r = idx >> 8, o = idx & 255;
        float inv = gout[o] * rsqrtf(vout[o] + 1e-5f);
        g_W2d[idx] = pk(s * inv * w_out[o * RED + r]);
    }
    if (tid < 256) {
        float inv = gout[tid] * rsqrtf(vout[tid] + 1e-5f);
        g_b2[tid] = s * (bout[tid] - mout[tid] * inv);
    }
    for (int idx = tid; idx < MID * 64; idx += 256) {
        int k = idx >> 6, o = idx & 63;
        g_Wqkd[idx] = pk((o < 32) ? qh[o * 32 + k] : kh[(o - 32) * 32 + k]);
    }
    if (tid < 64) g_bqk[tid] = (tid < 32) ? qb[tid] : kb[tid - 32];
}

// ---------------------------------------------------------------------------
// SMEM layout (floats), phase-overlaid:
//   A: xchunk(4096) -> dupWqk(4096) -> S(64x68=4352)
//   B: dupW1 sub-chunk(4096) -> [qs|ks](4096) -> dupW2 sub-chunk(4096)
//   C: xr(4096) -> attout(4096)
//   D: base(2048) -> outs(2048)
//   U: vs(2048)
// ---------------------------------------------------------------------------
#define SM_A    0
#define SM_B    4352
#define SM_C    8448
#define SM_D    12544
#define SM_U    14592
#define SM_WQK  16640
#define SM_WV   17152
#define SM_WO   17664
#define SM_BQK  18176
#define SM_BV   18240
#define SM_BO   18272
#define SM_B1   18336
#define SM_B2   18400
#define SM_TOTAL 18656   // 74624 bytes -> 3 CTAs/SM

__global__ __launch_bounds__(256, 3) void k_fused(
    const float* __restrict__ x, float* __restrict__ out,
    const float* __restrict__ wqk_g, const float* __restrict__ wv_g,
    const float* __restrict__ vb_g,  const float* __restrict__ wo_g,
    const float* __restrict__ ob_g)
{
    extern __shared__ float sm[];
    const int tid = threadIdx.x;
    const int bw = blockIdx.x;
    const int b  = bw >> 8;
    const int hb = (bw >> 4) & 15;
    const int wb = bw & 15;
    const long winbase = (long)(hb * 8) * 128 + wb * 8;
    const long xwin = (long)b * CCH * HWSZ + winbase;

    // ---- weights to smem ----
    for (int i = tid; i < 512; i += 256) {
        sm[SM_WQK + i] = wqk_g[i];
        sm[SM_WV + i]  = wv_g[i];
        sm[SM_WO + i]  = wo_g[i];
    }
    if (tid < 64)       sm[SM_BQK + tid] = g_bqk[tid];
    else if (tid < 96)  sm[SM_BV + tid - 64] = vb_g[tid - 64];
    else if (tid < 160) sm[SM_BO + tid - 96] = ob_g[tid - 96];
    else if (tid < 224) sm[SM_B1 + tid - 160] = g_b1[tid - 160];
    sm[SM_B2 + tid] = g_b2[tid];

    // GEMM thread mapping: warp 16o x 32n, thread 4o x 4n
    const int wid = tid >> 5, lane = tid & 31;
    const int o0 = (wid & 3) * 16 + (lane >> 3) * 4;
    const int n0 = (wid >> 2) * 32 + (lane & 7) * 4;
    const int nh = n0 >> 1;   // u64-pair index

    // ================= in_proj: xr = W1^T @ x_window (K=256) =================
    {
        u64t acc[4][2] = {{0,0},{0,0},{0,0},{0,0}};
        for (int kc = 0; kc < 4; kc++) {
            // stage x chunk (64 c x 64 n) into A
            for (int idx = tid; idx < 1024; idx += 256) {
                int c = idx >> 4, q = idx & 15;
                ((float4*)(sm + SM_A))[idx] =
                    *(const float4*)&x[xwin + (long)(kc * 64 + c) * HWSZ + ((q >> 1) << 7) + ((q & 1) << 2)];
            }
            for (int sub = 0; sub < 2; sub++) {
                // stage dup'd W sub-chunk (32 c x 64 o u64) into B
                {
                    const float4* src = (const float4*)(g_W1d + (kc * 64 + sub * 32) * 64);
                    for (int idx = tid; idx < 1024; idx += 256)
                        ((float4*)(sm + SM_B))[idx] = src[idx];
                }
                __syncthreads();
#pragma unroll 8
                for (int k = 0; k < 32; k++) {
                    const u64t* wp = (const u64t*)(sm + SM_B) + k * 64 + o0;
                    u64t w0 = wp[0], w1 = wp[1], w2 = wp[2], w3 = wp[3];
                    const u64t* xp = (const u64t*)(sm + SM_A + (sub * 32 + k) * 64) + nh;
                    u64t x0 = xp[0], x1 = xp[1];
                    f2fma(acc[0][0], w0, x0); f2fma(acc[0][1], w0, x1);
                    f2fma(acc[1][0], w1, x0); f2fma(acc[1][1], w1, x1);
                    f2fma(acc[2][0], w2, x0); f2fma(acc[2][1], w2, x1);
                    f2fma(acc[3][0], w3, x0); f2fma(acc[3][1], w3, x1);
                }
                __syncthreads();
            }
        }
#pragma unroll
        for (int i = 0; i < 4; i++) {
            u64t bd = pk(sm[SM_B1 + o0 + i]);
            f2add(acc[i][0], bd); f2add(acc[i][1], bd);
            *(ulonglong2*)(sm + SM_C + (o0 + i) * 64 + n0) =
                make_ulonglong2(acc[i][0], acc[i][1]);
        }
    }
    __syncthreads();

    // ====== base (wqk) + v (wv) grouped convs on xr; stage dupWqk -> A ======
    {
#pragma unroll
        for (int t2 = 0; t2 < 2; t2++) {
            int et = tid + 256 * t2;
            int m = et >> 4, nb = (et & 15) * 4, g = m >> 3;
            const float* wr1 = sm + SM_WQK + g * 128 + (m & 7) * 16;
            const float* wr2 = sm + SM_WV  + g * 128 + (m & 7) * 16;
            float bv = sm[SM_BV + m];
            float4 ab = make_float4(0.f, 0.f, 0.f, 0.f);
            float4 av = make_float4(bv, bv, bv, bv);
#pragma unroll
            for (int i = 0; i < 16; i++) {
                float w1 = wr1[i], w2 = wr2[i];
                float4 xv = *(const float4*)(sm + SM_C + (g * 16 + i) * 64 + nb);
                ab.x += w1 * xv.x; ab.y += w1 * xv.y; ab.z += w1 * xv.z; ab.w += w1 * xv.w;
                av.x += w2 * xv.x; av.y += w2 * xv.y; av.z += w2 * xv.z; av.w += w2 * xv.w;
            }
            *(float4*)(sm + SM_D + m * 64 + nb) = ab;
            *(float4*)(sm + SM_U + m * 64 + nb) = av;
        }
        const float4* src = (const float4*)g_Wqkd;
        for (int idx = tid; idx < 1024; idx += 256)
            ((float4*)(sm + SM_A))[idx] = src[idx];
    }
    __syncthreads();

    // ========== q|k : dense 64x64, K=32 GEMM on base ==========
    {
        u64t acc[4][2] = {{0,0},{0,0},{0,0},{0,0}};
#pragma unroll 8
        for (int k = 0; k < 32; k++) {
            const u64t* wp = (const u64t*)(sm + SM_A) + k * 64 + o0;
            u64t w0 = wp[0], w1 = wp[1], w2 = wp[2], w3 = wp[3];
            const u64t* xp = (const u64t*)(sm + SM_D + k * 64) + nh;
            u64t x0 = xp[0], x1 = xp[1];
            f2fma(acc[0][0], w0, x0); f2fma(acc[0][1], w0, x1);
            f2fma(acc[1][0], w1, x0); f2fma(acc[1][1], w1, x1);
            f2fma(acc[2][0], w2, x0); f2fma(acc[2][1], w2, x1);
            f2fma(acc[3][0], w3, x0); f2fma(acc[3][1], w3, x1);
        }
        __syncthreads();   // done reading A (reused as S next)
#pragma unroll
        for (int i = 0; i < 4; i++) {
            u64t bd = pk(sm[SM_BQK + o0 + i]);
            f2add(acc[i][0], bd); f2add(acc[i][1], bd);
            *(ulonglong2*)(sm + SM_B + (o0 + i) * 64 + n0) =
                make_ulonglong2(acc[i][0], acc[i][1]);
        }
    }
    __syncthreads();

    // ================= attention, per head =================
    for (int h = 0; h < 4; h++) {
        // scores 4x4 register tile -> S (stride 68)
        {
            float sc[4][4];
#pragma unroll
            for (int a = 0; a < 4; a++)
#pragma unroll
                for (int c = 0; c < 4; c++) sc[a][c] = 0.f;
#pragma unroll
            for (int d = 0; d < 8; d++) {
                float4 q4 = *(const float4*)(sm + SM_B + (h * 8 + d) * 64 + o0);
                float4 k4 = *(const float4*)(sm + SM_B + 2048 + (h * 8 + d) * 64 + n0);
                sc[0][0] += q4.x * k4.x; sc[0][1] += q4.x * k4.y; sc[0][2] += q4.x * k4.z; sc[0][3] += q4.x * k4.w;
                sc[1][0] += q4.y * k4.x; sc[1][1] += q4.y * k4.y; sc[1][2] += q4.y * k4.z; sc[1][3] += q4.y * k4.w;
                sc[2][0] += q4.z * k4.x; sc[2][1] += q4.z * k4.y; sc[2][2] += q4.z * k4.z; sc[2][3] += q4.z * k4.w;
                sc[3][0] += q4.w * k4.x; sc[3][1] += q4.w * k4.y; sc[3][2] += q4.w * k4.z; sc[3][3] += q4.w * k4.w;
            }
#pragma unroll
            for (int a = 0; a < 4; a++) {
                float4 ov = make_float4(sc[a][0] * ATT_SCALE, sc[a][1] * ATT_SCALE,
                                        sc[a][2] * ATT_SCALE, sc[a][3] * ATT_SCALE);
                *(float4*)(sm + SM_A + (o0 + a) * 68 + n0) = ov;
            }
        }
        __syncthreads();
        // softmax: 4 threads per row, shfl reduce
        {
            int row = tid >> 2, qd = tid & 3;
            float* Sr = sm + SM_A + row * 68 + qd * 16;
            float4 v0 = *(float4*)(Sr + 0), v1 = *(float4*)(Sr + 4);
            float4 v2 = *(float4*)(Sr + 8), v3 = *(float4*)(Sr + 12);
            float mx = fmaxf(fmaxf(fmaxf(v0.x, v0.y), fmaxf(v0.z, v0.w)),
                             fmaxf(fmaxf(v1.x, v1.y), fmaxf(v1.z, v1.w)));
            mx = fmaxf(mx, fmaxf(fmaxf(fmaxf(v2.x, v2.y), fmaxf(v2.z, v2.w)),
                                 fmaxf(fmaxf(v3.x, v3.y), fmaxf(v3.z, v3.w))));
            mx = fmaxf(mx, __shfl_xor_sync(0xffffffffu, mx, 1));
            mx = fmaxf(mx, __shfl_xor_sync(0xffffffffu, mx, 2));
            v0.x = __expf(v0.x - mx); v0.y = __expf(v0.y - mx); v0.z = __expf(v0.z - mx); v0.w = __expf(v0.w - mx);
            v1.x = __expf(v1.x - mx); v1.y = __expf(v1.y - mx); v1.z = __expf(v1.z - mx); v1.w = __expf(v1.w - mx);
            v2.x = __expf(v2.x - mx); v2.y = __expf(v2.y - mx); v2.z = __expf(v2.z - mx); v2.w = __expf(v2.w - mx);
            v3.x = __expf(v3.x - mx); v3.y = __expf(v3.y - mx); v3.z = __expf(v3.z - mx); v3.w = __expf(v3.w - mx);
            float s = (v0.x + v0.y + v0.z + v0.w) + (v1.x + v1.y + v1.z + v1.w)
                    + (v2.x + v2.y + v2.z + v2.w) + (v3.x + v3.y + v3.z + v3.w);
            s += __shfl_xor_sync(0xffffffffu, s, 1);
            s += __shfl_xor_sync(0xffffffffu, s, 2);
            float r = 1.f / s;
            v0.x *= r; v0.y *= r; v0.z *= r; v0.w *= r;
            v1.x *= r; v1.y *= r; v1.z *= r; v1.w *= r;
            v2.x *= r; v2.y *= r; v2.z *= r; v2.w *= r;
            v3.x *= r; v3.y *= r; v3.z *= r; v3.w *= r;
            *(float4*)(Sr + 0) = v0;  *(float4*)(Sr + 4) = v1;
            *(float4*)(Sr + 8) = v2;  *(float4*)(Sr + 12) = v3;
        }
        __syncthreads();
        // out = attn @ v : thread -> token i, rows r0, r0+1
        {
            int i = tid & 63, dq = tid >> 6;
            int r0 = h * 8 + dq * 2;
            const float* Sr = sm + SM_A + i * 68;
            float a0 = 0.f, a1 = 0.f;
#pragma unroll
            for (int j = 0; j < 64; j += 4) {
                float4 s4 = *(const float4*)(Sr + j);
                float4 w0 = *(const float4*)(sm + SM_U + r0 * 64 + j);
                float4 w1 = *(const float4*)(sm + SM_U + (r0 + 1) * 64 + j);
                a0 += s4.x * w0.x + s4.y * w0.y + s4.z * w0.z + s4.w * w0.w;
                a1 += s4.x * w1.x + s4.y * w1.y + s4.z * w1.z + s4.w * w1.w;
            }
            sm[SM_D + r0 * 64 + i]       = a0;
            sm[SM_D + (r0 + 1) * 64 + i] = a1;
        }
        __syncthreads();
    }

    // ========== o grouped conv (32 -> 64) -> attout in C ==========
#pragma unroll
    for (int t4 = 0; t4 < 4; t4++) {
        int et = tid + 256 * t4;
        int r = et >> 4, nb = (et & 15) * 4, g = r >> 4;
        const float* wr = sm + SM_WO + g * 128 + (r & 15) * 8;
        float bo = sm[SM_BO + r];
        float4 a = make_float4(bo, bo, bo, bo);
#pragma unroll
        for (int m = 0; m < 8; m++) {
            float w = wr[m];
            float4 xv = *(const float4*)(sm + SM_D + (g * 8 + m) * 64 + nb);
            a.x += w * xv.x; a.y += w * xv.y; a.z += w * xv.z; a.w += w * xv.w;
        }
        *(float4*)(sm + SM_C + r * 64 + nb) = a;
    }
    __syncthreads();

    // ========== out_proj (4 o-tiles of 64, K=64 in 2 sub-chunks) ==========
    const int ty0 = ((n0 >> 3) << 7);
    const int tx0 = (n0 & 7);
    for (int ot = 0; ot < 4; ot++) {
        u64t acc[4][2] = {{0,0},{0,0},{0,0},{0,0}};
        for (int sub = 0; sub < 2; sub++) {
            for (int idx = tid; idx < 1024; idx += 256) {
                int r = idx >> 5, oq = idx & 31;
                ((float4*)(sm + SM_B))[idx] =
                    ((const float4*)(g_W2d + (sub * 32 + r) * 256 + ot * 64))[oq];
            }
            __syncthreads();
#pragma unroll 8
            for (int k = 0; k < 32; k++) {
                const u64t* wp = (const u64t*)(sm + SM_B) + k * 64 + o0;
                u64t w0 = wp[0], w1 = wp[1], w2 = wp[2], w3 = wp[3];
                const u64t* xp = (const u64t*)(sm + SM_C + (sub * 32 + k) * 64) + nh;
                u64t x0 = xp[0], x1 = xp[1];
                f2fma(acc[0][0], w0, x0); f2fma(acc[0][1], w0, x1);
                f2fma(acc[1][0], w1, x0); f2fma(acc[1][1], w1, x1);
                f2fma(acc[2][0], w2, x0); f2fma(acc[2][1], w2, x1);
                f2fma(acc[3][0], w3, x0); f2fma(acc[3][1], w3, x1);
            }
            __syncthreads();
        }
#pragma unroll
        for (int i2 = 0; i2 < 4; i2++) {
            int o = ot * 64 + o0 + i2;
            long ga = xwin + (long)o * HWSZ + ty0 + tx0;
            float4 xi = *(const float4*)&x[ga];
            float bb = sm[SM_B2 + o];
            float2 lo = up(acc[i2][0]), hi = up(acc[i2][1]);
            float4 ov = make_float4(lo.x + bb + xi.x, lo.y + bb + xi.y,
                                    hi.x + bb + xi.z, hi.y + bb + xi.w);
            *(float4*)&out[ga] = ov;
        }
    }
}

// ---------------------------------------------------------------------------
extern "C" void kernel_launch(void* const* d_in, const int* in_sizes, int n_in,
                              void* d_out, int out_size)
{
    const float* x            = (const float*)d_in[0];
    const float* bn_in_gamma  = (const float*)d_in[1];
    const float* bn_in_beta   = (const float*)d_in[2];
    const float* bn_in_mean   = (const float*)d_in[3];
    const float* bn_in_var    = (const float*)d_in[4];
    const float* in_proj_w    = (const float*)d_in[5];
    const float* qk_base_w    = (const float*)d_in[6];
    const float* q_head_w     = (const float*)d_in[7];
    const float* q_head_b     = (const float*)d_in[8];
    const float* k_head_w     = (const float*)d_in[9];
    const float* k_head_b     = (const float*)d_in[10];
    const float* v_w          = (const float*)d_in[11];
    const float* v_b          = (const float*)d_in[12];
    const float* o_w          = (const float*)d_in[13];
    const float* o_b          = (const float*)d_in[14];
    const float* out_proj_w   = (const float*)d_in[15];
    const float* bn_out_gamma = (const float*)d_in[16];
    const float* bn_out_beta  = (const float*)d_in[17];
    const float* bn_out_mean  = (const float*)d_in[18];
    const float* bn_out_var   = (const float*)d_in[19];
    const float* alpha        = (const float*)d_in[20];

    float* out = (float*)d_out;

    k_prep<<<1, 256>>>(bn_in_gamma, bn_in_beta, bn_in_mean, bn_in_var,
                       in_proj_w, out_proj_w,
                       bn_out_gamma, bn_out_beta, bn_out_mean, bn_out_var,
                       alpha, q_head_w, q_head_b, k_head_w, k_head_b);

    cudaFuncSetAttribute(k_fused, cudaFuncAttributeMaxDynamicSharedMemorySize,
                         SM_TOTAL * 4);
    k_fused<<<NWIN, 256, SM_TOTAL * 4>>>(x, out,
                                         qk_base_w, v_w, v_b, o_w, o_b);
}